// round 1
// baseline (speedup 1.0000x reference)
#include <cuda_runtime.h>

#define SS   128
#define TT   2048
#define BBATCH 64
#define DM   128
#define NEGF (-1.0e30f)
#define LOG2E 1.4426950408889634f
#define LN2F  0.6931471805599453f

// Precomputed parameter transforms (shared by all batches).
__device__ float g_expA2[SS * SS];   // exp2(A_logits * log2e), [i][j]
__device__ float g_D2t[DM * SS];     // D_logits^T * log2e, [d][j]
__device__ float g_pi2[SS];          // pi_logits * log2e

__device__ __forceinline__ float ex2f(float x) {
    float y; asm("ex2.approx.ftz.f32 %0, %1;" : "=f"(y) : "f"(x)); return y;
}
__device__ __forceinline__ float lg2f(float x) {
    float y; asm("lg2.approx.ftz.f32 %0, %1;" : "=f"(y) : "f"(x)); return y;
}

__global__ void hsmm_precompute(const float* __restrict__ A,
                                const float* __restrict__ D,
                                const float* __restrict__ pi) {
    int r = blockIdx.x;      // 0..127
    int j = threadIdx.x;     // 0..127
    g_expA2[r * SS + j] = ex2f(A[r * SS + j] * LOG2E);
    // transpose D: g_D2t[d][j] = D[j][d]
    g_D2t[r * SS + j] = D[j * DM + r] * LOG2E;
    if (r == 0) g_pi2[j] = pi[j] * LOG2E;
}

// Dynamic smem layout (floats): D2s[16384] | Er[16384] | psh[128] | wred[8]
#define SMEM_FLOATS (SS * DM + SS * DM + SS + 8)
#define SMEM_BYTES  (SMEM_FLOATS * 4)

__global__ __launch_bounds__(128, 1)
void hsmm_kernel(const float* __restrict__ logB, float* __restrict__ out) {
    extern __shared__ float sm[];
    float* D2s  = sm;                 // [d][j], log2-domain durations
    float* Er   = sm + SS * DM;       // E ring, [slot][j]; thread j owns column j
    float* psh  = Er + SS * DM;       // exp2(alpha - m)
    float* wred = psh + SS;           // cross-warp reduction scratch

    const int j    = threadIdx.x;
    const int b    = blockIdx.x;
    const int lane = j & 31;
    const int wid  = j >> 5;

    // A column j in registers: regA[i] = exp2(A2[i][j])
    float regA[SS];
#pragma unroll
    for (int i = 0; i < SS; ++i) regA[i] = g_expA2[i * SS + j];

    for (int k = j; k < SS * DM; k += SS) {
        D2s[k] = g_D2t[k];
        Er[k]  = NEGF;
    }

    const float pi2j = g_pi2[j];
    const float* lbp = logB + (size_t)b * TT * SS + j;

    float cum2   = 0.0f;   // log2 prefix sum of emissions for state j
    float g_prev = NEGF;   // previous duration-lse (log2)
    float a_j    = NEGF;   // alpha[t][j] (log2)

    float lb_next = lbp[0] * LOG2E;
    __syncthreads();

    for (int t = 0; t < TT; ++t) {
        float lb_cur = lb_next;
        lb_next = lbp[(size_t)min(t + 1, TT - 1) * SS] * LOG2E;  // prefetch

        float entry;
        if (t > 0) {
            // block max of alpha_prev via shfl + smem
            float wm = a_j;
#pragma unroll
            for (int o = 16; o; o >>= 1)
                wm = fmaxf(wm, __shfl_xor_sync(0xffffffffu, wm, o));
            if (lane == 0) wred[wid] = wm;
            __syncthreads();
            float m2 = fmaxf(fmaxf(wred[0], wred[1]), fmaxf(wred[2], wred[3]));
            psh[j] = ex2f(a_j - m2);
            __syncthreads();

            // trans[j] = m2 + log2( sum_i p[i] * exp2(A2[i][j]) )
            const float4* p4 = (const float4*)psh;
            float s0 = 0.f, s1 = 0.f, s2 = 0.f, s3 = 0.f;
#pragma unroll
            for (int i = 0; i < SS; i += 4) {
                float4 pv = p4[i >> 2];
                s0 = fmaf(pv.x, regA[i + 0], s0);
                s1 = fmaf(pv.y, regA[i + 1], s1);
                s2 = fmaf(pv.z, regA[i + 2], s2);
                s3 = fmaf(pv.w, regA[i + 3], s3);
            }
            entry = m2 + lg2f((s0 + s1) + (s2 + s3));
        } else {
            entry = pi2j;
        }

        // E[t][j] = entry - cum[t]; own-column ring write, no barrier needed
        float Enew = entry - cum2;
        Er[(t & 127) * SS + j] = Enew;

        // shift: s >= max_d x_d - (max adjacent D gap); single-pass lse
        float s = fmaxf(g_prev, Enew + D2s[j]);
        float c0 = 0.f, c1 = 0.f, c2 = 0.f, c3 = 0.f;
#pragma unroll 2
        for (int dd = 0; dd < DM; dd += 4) {
            float x0 = Er[((t - dd    ) & 127) * SS + j] + D2s[(dd    ) * SS + j];
            float x1 = Er[((t - dd - 1) & 127) * SS + j] + D2s[(dd + 1) * SS + j];
            float x2 = Er[((t - dd - 2) & 127) * SS + j] + D2s[(dd + 2) * SS + j];
            float x3 = Er[((t - dd - 3) & 127) * SS + j] + D2s[(dd + 3) * SS + j];
            c0 += ex2f(x0 - s);
            c1 += ex2f(x1 - s);
            c2 += ex2f(x2 - s);
            c3 += ex2f(x3 - s);
        }
        g_prev = s + lg2f((c0 + c1) + (c2 + c3));

        cum2 += lb_cur;          // now cum[t+1]
        a_j = cum2 + g_prev;     // alpha[t][j]
    }

    // loglik[b] = ln2 * log2sumexp2_j alpha[T-1][j]
    float wm = a_j;
#pragma unroll
    for (int o = 16; o; o >>= 1)
        wm = fmaxf(wm, __shfl_xor_sync(0xffffffffu, wm, o));
    if (lane == 0) wred[wid] = wm;
    __syncthreads();
    float m2 = fmaxf(fmaxf(wred[0], wred[1]), fmaxf(wred[2], wred[3]));
    float pe = ex2f(a_j - m2);
#pragma unroll
    for (int o = 16; o; o >>= 1)
        pe += __shfl_xor_sync(0xffffffffu, pe, o);
    if (lane == 0) wred[4 + wid] = pe;
    __syncthreads();
    if (j == 0) {
        float ssum = (wred[4] + wred[5]) + (wred[6] + wred[7]);
        out[b] = (m2 + lg2f(ssum)) * LN2F;
    }
}

extern "C" void kernel_launch(void* const* d_in, const int* in_sizes, int n_in,
                              void* d_out, int out_size) {
    const float* logB = (const float*)d_in[0];  // (B, T, S)
    const float* pi   = (const float*)d_in[1];  // (S,)
    const float* A    = (const float*)d_in[2];  // (S, S)
    const float* D    = (const float*)d_in[3];  // (S, DMAX)

    hsmm_precompute<<<128, 128>>>(A, D, pi);

    cudaFuncSetAttribute(hsmm_kernel,
                         cudaFuncAttributeMaxDynamicSharedMemorySize, SMEM_BYTES);
    hsmm_kernel<<<BBATCH, 128, SMEM_BYTES>>>(logB, (float*)d_out);
}

// round 2
// speedup vs baseline: 2.0983x; 2.0983x over previous
#include <cuda_runtime.h>

#define SS   128
#define TT   2048
#define BB   64
#define DM   128
#define LOG2E 1.4426950408889634f
#define LN2F  0.6931471805599453f
#define RS_MASK 31   // ring rescale every 32 steps
#define M2_MASK 15   // block-max refresh every 16 steps

// Static parameter transforms (shared across batches).
__device__ float g_expA[SS * SS];  // e^{A[i][j]}, layout [i][j]
__device__ float g_expD[DM * SS];  // e^{D[j][d]}, layout [d][j]
__device__ float g_pi2[SS];        // pi * log2e

__device__ __forceinline__ float ex2f(float x) {
    float y; asm("ex2.approx.ftz.f32 %0, %1;" : "=f"(y) : "f"(x)); return y;
}
__device__ __forceinline__ float lg2f(float x) {
    float y; asm("lg2.approx.ftz.f32 %0, %1;" : "=f"(y) : "f"(x)); return y;
}

__global__ void hsmm_precompute(const float* __restrict__ A,
                                const float* __restrict__ D,
                                const float* __restrict__ pi) {
    int r = blockIdx.x;   // 0..127
    int j = threadIdx.x;  // 0..127
    g_expA[r * SS + j] = expf(A[r * SS + j]);
    g_expD[r * SS + j] = expf(D[j * DM + r]);   // transpose
    if (r == 0) g_pi2[j] = pi[j] * LOG2E;
}

// Dynamic smem (floats):
//   Er[128*128] | psh[128] | tpart[512] | psum[512] | pmax[512] | rs[128] | wred[8]
#define OFF_ER    0
#define OFF_PSH   (SS * 128)
#define OFF_TPART (OFF_PSH + SS)
#define OFF_PSUM  (OFF_TPART + 4 * SS)
#define OFF_PMAX  (OFF_PSUM + 4 * SS)
#define OFF_RS    (OFF_PMAX + 4 * SS)
#define OFF_WRED  (OFF_RS + SS)
#define SMEM_FLOATS (OFF_WRED + 8)
#define SMEM_BYTES  (SMEM_FLOATS * 4)

__global__ __launch_bounds__(512, 1)
void hsmm_kernel(const float* __restrict__ logB, float* __restrict__ out) {
    extern __shared__ float sm[];
    float* Er    = sm + OFF_ER;     // exp-domain entry ring, [slot][j]
    float* psh   = sm + OFF_PSH;    // 2^(alpha - m2)
    float* tpart = sm + OFF_TPART;  // trans partials [j*4 + c]
    float* psum  = sm + OFF_PSUM;   // dot partials   [j*4 + c]
    float* pmax  = sm + OFF_PMAX;   // ring-max partials (rescale steps)
    float* rs    = sm + OFF_RS;     // rescale factor per state
    float* wred  = sm + OFF_WRED;

    const int tid  = threadIdx.x;
    const int j    = tid & 127;
    const int c    = tid >> 7;       // 0..3: d-band / i-band index
    const int lane = tid & 31;
    const int wrp  = tid >> 5;

    // Static params for this (c, j): 32-wide chunks in registers.
    float regA[32], regD[32];
#pragma unroll
    for (int q = 0; q < 32; ++q) {
        regA[q] = g_expA[(32 * c + q) * SS + j];
        regD[q] = g_expD[(32 * c + q) * SS + j];
    }

    // Zero ring (exp-domain: 0 == -inf sentinel, masks d > t+1 for free).
    for (int k = tid; k < 128 * SS; k += 512) Er[k] = 0.0f;

    const float pi2j = g_pi2[j];
    const float* lbp = logB + (size_t)blockIdx.x * TT * SS + j;

    // c==0 per-state registers
    float cum2 = 0.0f, R = 0.0f, alpha = 0.0f, m2h = 0.0f;
    float lb_cur = 0.0f;
    if (c == 0) lb_cur = lbp[0] * LOG2E;
    __syncthreads();

    for (int t = 0; t < TT; ++t) {
        const bool resc = ((t & RS_MASK) == RS_MASK) && (t < TT - 1);

        // ---- C' phase: entry/v_new (c==0) + dot partials (all) ----
        float lb_new = 0.0f;
        if (c == 0) {
            lb_new = lbp[(size_t)min(t + 1, TT - 1) * SS] * LOG2E;  // prefetch
            float entry;
            if (t == 0) {
                entry = pi2j;
            } else {
                float4 tp = *(const float4*)(tpart + 4 * j);
                entry = m2h + lg2f((tp.x + tp.y) + (tp.z + tp.w));
            }
            float Enew = entry - cum2;
            float vnew = ex2f(Enew - R);
            Er[((t & 127) << 7) + j] = vnew;
            cum2 += lb_cur;                 // cum[t+1] in log2
        }
        {
            // band c covers d = 32c+1 .. 32c+32  -> slots (t - 32c - q) & 127
            const int base = t - 32 * c;
            float a0 = 0.f, a1 = 0.f, a2 = 0.f, a3 = 0.f;
            float mx = 0.f;
#pragma unroll
            for (int q = 0; q < 32; q += 4) {
                float v0 = Er[(((base - q    ) & 127) << 7) + j];
                float v1 = Er[(((base - q - 1) & 127) << 7) + j];
                float v2 = Er[(((base - q - 2) & 127) << 7) + j];
                float v3 = Er[(((base - q - 3) & 127) << 7) + j];
                a0 = fmaf(v0, regD[q    ], a0);
                a1 = fmaf(v1, regD[q + 1], a1);
                a2 = fmaf(v2, regD[q + 2], a2);
                a3 = fmaf(v3, regD[q + 3], a3);
                if (resc) mx = fmaxf(mx, fmaxf(fmaxf(v0, v1), fmaxf(v2, v3)));
            }
            psum[4 * j + c] = (a0 + a1) + (a2 + a3);
            if (resc) pmax[4 * j + c] = mx;
        }
        __syncthreads();  // bar1: psum (+ring slot t) visible

        // ---- D phase: combine, alpha, psh, rescale factor (c==0) ----
        if (c == 0) {
            float4 ps = *(const float4*)(psum + 4 * j);
            float dot = (ps.x + ps.y) + (ps.z + ps.w);
            float g = R + lg2f(dot);
            alpha = cum2 + g;
            if (resc) {
                float4 pm = *(const float4*)(pmax + 4 * j);
                float mv = fmaxf(fmaxf(pm.x, pm.y), fmaxf(pm.z, pm.w));
                float dlt = lg2f(mv);
                R += dlt;
                rs[j] = ex2f(-dlt);
            }
            if ((t & M2_MASK) == M2_MASK) {
                float wm = alpha;
#pragma unroll
                for (int o = 16; o; o >>= 1)
                    wm = fmaxf(wm, __shfl_xor_sync(0xffffffffu, wm, o));
                if (lane == 0) wred[wrp] = wm;
                asm volatile("bar.sync 1, 128;" ::: "memory");
                m2h = fmaxf(fmaxf(wred[0], wred[1]), fmaxf(wred[2], wred[3]));
            }
            psh[j] = ex2f(alpha - m2h);
        }
        __syncthreads();  // bar2: psh, rs visible

        // ---- A phase: trans partials for t+1 + ring rescale pass ----
        if (t < TT - 1) {
            const float4* p4 = (const float4*)psh;
            float s0 = 0.f, s1 = 0.f, s2 = 0.f, s3 = 0.f;
#pragma unroll
            for (int q = 0; q < 32; q += 4) {
                float4 pv = p4[(32 * c + q) >> 2];   // broadcast
                s0 = fmaf(pv.x, regA[q    ], s0);
                s1 = fmaf(pv.y, regA[q + 1], s1);
                s2 = fmaf(pv.z, regA[q + 2], s2);
                s3 = fmaf(pv.w, regA[q + 3], s3);
            }
            tpart[4 * j + c] = (s0 + s1) + (s2 + s3);
            if (resc) {
                float f = rs[j];
#pragma unroll
                for (int r = 0; r < 32; ++r)
                    Er[((32 * c + r) << 7) + j] *= f;
            }
        }
        __syncthreads();  // bar3: tpart + rescaled ring visible

        lb_cur = lb_new;
    }

    // loglik[b] = ln2 * log2sumexp2_j alpha[T-1][j]   (alpha lives in c==0)
    float m2f = 0.0f;
    if (c == 0) {
        float wm = alpha;
#pragma unroll
        for (int o = 16; o; o >>= 1)
            wm = fmaxf(wm, __shfl_xor_sync(0xffffffffu, wm, o));
        if (lane == 0) wred[wrp] = wm;
    }
    __syncthreads();
    if (c == 0) {
        m2f = fmaxf(fmaxf(wred[0], wred[1]), fmaxf(wred[2], wred[3]));
        float pe = ex2f(alpha - m2f);
#pragma unroll
        for (int o = 16; o; o >>= 1)
            pe += __shfl_xor_sync(0xffffffffu, pe, o);
        if (lane == 0) wred[4 + wrp] = pe;
    }
    __syncthreads();
    if (tid == 0) {
        float ssum = (wred[4] + wred[5]) + (wred[6] + wred[7]);
        out[blockIdx.x] = (m2f + lg2f(ssum)) * LN2F;
    }
}

extern "C" void kernel_launch(void* const* d_in, const int* in_sizes, int n_in,
                              void* d_out, int out_size) {
    const float* logB = (const float*)d_in[0];  // (B, T, S)
    const float* pi   = (const float*)d_in[1];  // (S,)
    const float* A    = (const float*)d_in[2];  // (S, S)
    const float* D    = (const float*)d_in[3];  // (S, DMAX)

    hsmm_precompute<<<128, 128>>>(A, D, pi);

    cudaFuncSetAttribute(hsmm_kernel,
                         cudaFuncAttributeMaxDynamicSharedMemorySize, SMEM_BYTES);
    hsmm_kernel<<<BB, 512, SMEM_BYTES>>>(logB, (float*)d_out);
}

// round 4
// speedup vs baseline: 2.3255x; 1.1083x over previous
#include <cuda_runtime.h>

#define SS   128
#define TT   2048
#define BB   64
#define DM   128
#define LOG2E 1.4426950408889634f
#define LN2F  0.6931471805599453f

typedef unsigned long long ull;

// Static parameter transforms (shared across batches).
__device__ float g_expA[SS * SS];  // e^{A[i][j]}, [i][j]
__device__ float g_expD[DM * SS];  // e^{D[j][d-1]}, [d-1][j] (transposed)
__device__ float g_pi2[SS];        // pi * log2e

__device__ __forceinline__ float ex2f(float x) {
    float y; asm("ex2.approx.ftz.f32 %0, %1;" : "=f"(y) : "f"(x)); return y;
}
__device__ __forceinline__ float lg2f(float x) {
    float y; asm("lg2.approx.ftz.f32 %0, %1;" : "=f"(y) : "f"(x)); return y;
}
__device__ __forceinline__ ull packf2(float lo, float hi) {
    ull u; asm("mov.b64 %0, {%1, %2};" : "=l"(u) : "f"(lo), "f"(hi)); return u;
}
__device__ __forceinline__ void unpackf2(ull u, float& lo, float& hi) {
    asm("mov.b64 {%0, %1}, %2;" : "=f"(lo), "=f"(hi) : "l"(u));
}
__device__ __forceinline__ void ffma2(ull& d, ull a, ull b) {
    asm("fma.rn.f32x2 %0, %1, %2, %0;" : "+l"(d) : "l"(a), "l"(b));
}

__global__ void hsmm_precompute(const float* __restrict__ A,
                                const float* __restrict__ D,
                                const float* __restrict__ pi) {
    int r = blockIdx.x;   // 0..127
    int j = threadIdx.x;  // 0..127
    g_expA[r * SS + j] = expf(A[r * SS + j]);
    g_expD[r * SS + j] = expf(D[j * DM + r]);   // transpose; row r = duration r+1
    if (r == 0) g_pi2[j] = pi[j] * LOG2E;
}

// Smem layout (floats). Rings are [word][state] of float2; 80 words (64 + 16 mirror).
#define RING_W   80
#define OFF_RA   0
#define OFF_RB   (RING_W * 128 * 2)            // 20480
#define OFF_PSH  (OFF_RB + RING_W * 128 * 2)   // 40960
#define OFF_TP   (OFF_PSH + 128)               // 41088
#define OFF_PS   (OFF_TP + 512)                // 41600
#define OFF_PM   (OFF_PS + 512)                // 42112
#define OFF_RS   (OFF_PM + 512)                // 42624
#define OFF_WR   (OFF_RS + 128)                // 42752
#define SMEM_FLOATS (OFF_WR + 8)
#define SMEM_BYTES  (SMEM_FLOATS * 4)

__global__ __launch_bounds__(512, 1)
void hsmm_kernel(const float* __restrict__ logB, float* __restrict__ out) {
    extern __shared__ float sm[];
    ull*   RA    = (ull*)sm;                  // pairs (v[2m], v[2m+1])
    ull*   RB    = (ull*)(sm + OFF_RB);       // pairs (v[2m+1], v[2m+2])
    float* psh   = sm + OFF_PSH;
    float* tpart = sm + OFF_TP;               // [c][j]
    float* psum  = sm + OFF_PS;               // [c][j]
    float* pmax  = sm + OFF_PM;               // [c][j]
    float* rs    = sm + OFF_RS;
    float* wred  = sm + OFF_WR;

    const int tid  = threadIdx.x;
    const int j    = tid & 127;
    const int c    = tid >> 7;      // band index 0..3
    const int lane = tid & 31;
    const int wrp  = tid >> 5;

    // Static packed params. Dot band c covers d = 32c+2 .. 32c+33 (c=3: ..128, d=129 -> 0).
    ull regA2[16], regD2[16];
#pragma unroll
    for (int k = 0; k < 16; ++k) {
        int i0 = 32 * c + 2 * k;
        regA2[k] = packf2(g_expA[i0 * SS + j], g_expA[(i0 + 1) * SS + j]);
        int dHi = 32 * c + 33 - 2 * k;           // coeff for lower slot of word k
        float x = (dHi <= 128) ? g_expD[(dHi - 1) * SS + j] : 0.0f;
        float y = g_expD[(dHi - 2) * SS + j];    // dLo = dHi-1  (>= 2)
        regD2[k] = packf2(x, y);
    }

    // Zero rings (0 == exp-domain -inf; masks d > t+1) and psh.
    for (int k2 = tid; k2 < RING_W * 128; k2 += 512) { RA[k2] = 0ull; RB[k2] = 0ull; }
    if (tid < 128) psh[tid] = 0.0f;

    const float pi2j = g_pi2[j];
    const float eD1j = g_expD[j];                 // duration d=1
    const float* lbp = logB + (size_t)blockIdx.x * TT * SS + j;

    float cum2 = 0.f, R = 0.f, m2h = 0.f, alpha = 0.f, lb_cur = 0.f;
    if (c == 0) lb_cur = lbp[0] * LOG2E;
    __syncthreads();

    for (int t = 0; t < TT; ++t) {
        const bool resc = ((t & 31) == 31) && (t < TT - 1);

        // ---- X: duration dot (d>=2) + transition matvec, fully parallel ----
        {
            // window of 32 slots [t-32c-32, t-32c-1]; parity-phased ring select
            int tb = t + 4096 - 32 * c - 32 - (t & 1);
            int m0 = (tb >> 1) & 63;
            const ull* rp = ((t & 1) ? RB : RA) + (m0 << 7) + j;

            ull a0 = 0ull, a1 = 0ull;
#pragma unroll
            for (int k = 0; k < 16; k += 2) {
                ull v0 = rp[(k    ) << 7];
                ull v1 = rp[(k + 1) << 7];
                ffma2(a0, v0, regD2[k]);
                ffma2(a1, v1, regD2[k + 1]);
            }
            float l0, h0, l1, h1;
            unpackf2(a0, l0, h0); unpackf2(a1, l1, h1);
            psum[(c << 7) + j] = (l0 + h0) + (l1 + h1);

            // trans partial: sum_{i in band} psh[i] * e^{A[i][j]}
            const float4* p4 = (const float4*)psh;
            ull s0 = 0ull, s1 = 0ull;
#pragma unroll
            for (int k = 0; k < 8; ++k) {
                float4 v = p4[8 * c + k];
                ffma2(s0, packf2(v.x, v.y), regA2[2 * k]);
                ffma2(s1, packf2(v.z, v.w), regA2[2 * k + 1]);
            }
            float q0, q1, q2, q3;
            unpackf2(s0, q0, q1); unpackf2(s1, q2, q3);
            tpart[(c << 7) + j] = (q0 + q1) + (q2 + q3);

            if (resc) {   // ring max partial (rare path)
                float mx = 0.f;
#pragma unroll
                for (int k = 0; k < 16; ++k) {
                    float lo, hi; unpackf2(rp[k << 7], lo, hi);
                    mx = fmaxf(mx, fmaxf(lo, hi));
                }
                pmax[(c << 7) + j] = mx;
            }
        }
        __syncthreads();   // bar1

        // ---- Y: per-state scalar recurrence (128 threads) ----
        if (c == 0) {
            float lb_new = lbp[(size_t)min(t + 1, TT - 1) * SS] * LOG2E;  // prefetch

            float entry;
            if (t == 0) entry = pi2j;
            else entry = m2h + lg2f((tpart[j] + tpart[128 + j]) +
                                    (tpart[256 + j] + tpart[384 + j]));
            float vnew = ex2f(entry - cum2 - R);

            // ring writes (slot s = t mod 128), with mirror for words < 16
            int s  = t & 127;
            int wa = s >> 1;
            sm[OFF_RA + (wa << 8) + (j << 1) + (s & 1)] = vnew;
            if (wa < 16)
                sm[OFF_RA + ((wa + 64) << 8) + (j << 1) + (s & 1)] = vnew;
            int bw = (s & 1) ? wa : ((wa + 63) & 63);
            sm[OFF_RB + (bw << 8) + (j << 1) + ((s & 1) ^ 1)] = vnew;
            if (bw < 16)
                sm[OFF_RB + ((bw + 64) << 8) + (j << 1) + ((s & 1) ^ 1)] = vnew;

            float dot = (psum[j] + psum[128 + j]) + (psum[256 + j] + psum[384 + j])
                      + vnew * eD1j;
            cum2 += lb_cur;                       // cum[t+1] in log2

            if (((t & 15) == 15) || (t == TT - 1)) {
                alpha = cum2 + R + lg2f(dot);     // uses pre-rescale R
                if ((t & 15) == 15) {             // refresh m2h
                    float wm = alpha;
#pragma unroll
                    for (int o = 16; o; o >>= 1)
                        wm = fmaxf(wm, __shfl_xor_sync(0xffffffffu, wm, o));
                    if (lane == 0) wred[wrp] = wm;
                    asm volatile("bar.sync 1, 128;" ::: "memory");
                    m2h = fmaxf(fmaxf(wred[0], wred[1]), fmaxf(wred[2], wred[3]));
                }
            }
            // psh = 2^(alpha - m2h) without materializing alpha
            psh[j] = dot * ex2f(cum2 + R - m2h);

            if (resc) {
                float mv = fmaxf(fmaxf(pmax[j], pmax[128 + j]),
                                 fmaxf(pmax[256 + j], pmax[384 + j]));
                mv = fmaxf(mv, vnew);
                float dlt = lg2f(mv);
                R += dlt;
                rs[j] = ex2f(-dlt);
            }
            lb_cur = lb_new;
        }
        __syncthreads();   // bar2

        if (resc) {        // Z: rescale both rings (incl. mirrors) by per-state factor
            float f = rs[j];
            float2* ra2 = (float2*)RA;
            float2* rb2 = (float2*)RB;
#pragma unroll
            for (int w = 0; w < 20; ++w) {
                int idx = ((20 * c + w) << 7) + j;
                float2 va = ra2[idx]; va.x *= f; va.y *= f; ra2[idx] = va;
                float2 vb = rb2[idx]; vb.x *= f; vb.y *= f; rb2[idx] = vb;
            }
            __syncthreads();
        }
    }

    // loglik[b] = ln2 * log2sumexp2_j alpha[T-1][j]  (alpha lives in c==0)
    if (c == 0) {
        float wm = alpha;
#pragma unroll
        for (int o = 16; o; o >>= 1)
            wm = fmaxf(wm, __shfl_xor_sync(0xffffffffu, wm, o));
        if (lane == 0) wred[wrp] = wm;
    }
    __syncthreads();
    if (c == 0) {
        float m2f = fmaxf(fmaxf(wred[0], wred[1]), fmaxf(wred[2], wred[3]));
        float pe = ex2f(alpha - m2f);
#pragma unroll
        for (int o = 16; o; o >>= 1)
            pe += __shfl_xor_sync(0xffffffffu, pe, o);
        if (lane == 0) wred[4 + wrp] = pe;
        asm volatile("bar.sync 1, 128;" ::: "memory");
        if (tid == 0) {
            float ssum = (wred[4] + wred[5]) + (wred[6] + wred[7]);
            out[blockIdx.x] = (m2f + lg2f(ssum)) * LN2F;
        }
    }
}

extern "C" void kernel_launch(void* const* d_in, const int* in_sizes, int n_in,
                              void* d_out, int out_size) {
    const float* logB = (const float*)d_in[0];  // (B, T, S)
    const float* pi   = (const float*)d_in[1];  // (S,)
    const float* A    = (const float*)d_in[2];  // (S, S)
    const float* D    = (const float*)d_in[3];  // (S, DMAX)

    hsmm_precompute<<<128, 128>>>(A, D, pi);

    cudaFuncSetAttribute(hsmm_kernel,
                         cudaFuncAttributeMaxDynamicSharedMemorySize, SMEM_BYTES);
    hsmm_kernel<<<BB, 512, SMEM_BYTES>>>(logB, (float*)d_out);
}

// round 5
// speedup vs baseline: 3.1922x; 1.3727x over previous
#include <cuda_runtime.h>

#define SS   128
#define TT   2048
#define BB   64
#define NBLK 256              // TT / 8
#define LOG2E 1.4426950408889634f
#define LN2F  0.6931471805599453f

typedef unsigned long long ull;

// Static parameter transforms (shared across batches).
__device__ float g_expA[SS * SS];  // e^{A[i][j]}, [i][j]
__device__ float g_expD[SS * SS];  // e^{D[j][d-1]}, [d-1][j] (transposed)
__device__ float g_pi2[SS];        // pi * log2e

__device__ __forceinline__ float ex2f(float x) {
    float y; asm("ex2.approx.ftz.f32 %0, %1;" : "=f"(y) : "f"(x)); return y;
}
__device__ __forceinline__ float lg2f(float x) {
    float y; asm("lg2.approx.ftz.f32 %0, %1;" : "=f"(y) : "f"(x)); return y;
}
__device__ __forceinline__ ull packf2(float lo, float hi) {
    ull u; asm("mov.b64 %0, {%1, %2};" : "=l"(u) : "f"(lo), "f"(hi)); return u;
}
__device__ __forceinline__ void unpackf2(ull u, float& lo, float& hi) {
    asm("mov.b64 {%0, %1}, %2;" : "=f"(lo), "=f"(hi) : "l"(u));
}
__device__ __forceinline__ void ffma2(ull& d, ull a, ull b) {
    asm("fma.rn.f32x2 %0, %1, %2, %0;" : "+l"(d) : "l"(a), "l"(b));
}

__global__ void hsmm_precompute(const float* __restrict__ A,
                                const float* __restrict__ D,
                                const float* __restrict__ pi) {
    int r = blockIdx.x;   // 0..127
    int j = threadIdx.x;  // 0..127
    g_expA[r * SS + j] = expf(A[r * SS + j]);
    g_expD[r * SS + j] = expf(D[j * SS + r]);   // transpose; row r = duration r+1
    if (r == 0) g_pi2[j] = pi[j] * LOG2E;
}

// Smem layout (floats):
#define OFF_RING 0                    // ring[128][128]           16384
#define OFF_PSH  16384                // psh[128]
#define OFF_TP   16512                // tpart[2][128]
#define OFF_DF   16768                // dfar[2][4][8][128]       8192
#define OFF_PM   24960                // pmax[4][128]
#define OFF_RS   25472                // rs[128]
#define OFF_WR   25600                // wred[8]
#define SMEM_FLOATS 25608
#define SMEM_BYTES  (SMEM_FLOATS * 4)

__global__ __launch_bounds__(512, 1)
void hsmm_kernel(const float* __restrict__ logB, float* __restrict__ out) {
    extern __shared__ float sm[];
    float* ring = sm + OFF_RING;
    float* psh  = sm + OFF_PSH;
    float* tp   = sm + OFF_TP;
    float* dfar = sm + OFF_DF;
    float* pmax = sm + OFF_PM;
    float* rs   = sm + OFF_RS;
    float* wred = sm + OFF_WR;

    const int tid = threadIdx.x;
    const int j   = tid & 127;
    const int cq  = tid >> 7;          // quarter index 0..3

    // Role-specific static data, overlaid in one array to bound registers.
    //  tid <  256 (matvec/serial): P[0..31] = eA pairs for i-band [64*cq, 64*cq+64)
    //  tid >= 256 (conv):          P[0..27] = eD pairs for its 28-duration band
    ull   P[32];
    float eDn[16];
    int cp = 0, cb = 0;
    if (tid < 256) {
#pragma unroll
        for (int k = 0; k < 32; ++k)
            P[k] = packf2(g_expA[(64 * cq + 2 * k) * SS + j],
                          g_expA[(64 * cq + 2 * k + 1) * SS + j]);
#pragma unroll
        for (int d = 0; d < 16; ++d) eDn[d] = g_expD[d * SS + j];
    } else {
        int g = tid - 256; cp = g & 63; cb = g >> 6;   // state pair, duration band
        int d0 = 17 + 28 * cb;                          // durations d0..d0+27
#pragma unroll
        for (int q = 0; q < 28; ++q)
            P[q] = *(const ull*)&g_expD[(d0 + q - 1) * SS + 2 * cp];
    }

    // Zero ring (exp-domain 0 == -inf; masks d > t+1), psh, dfar.
    for (int k = tid; k < 16384; k += 512) ring[k] = 0.0f;
    for (int k = tid; k < 8192;  k += 512) dfar[k] = 0.0f;
    if (tid < 128) psh[tid] = 0.0f;

    const float* lbp = logB + (size_t)blockIdx.x * TT * SS + j;
    const float pi2j = (tid < 128) ? g_pi2[j] : 0.0f;

    float cum2 = 0.f, R = 0.f, m2h = 0.f, alpha = 0.f;
    float lb0 = 0.f, lb1 = 0.f;
    if (tid < 128) { lb0 = lbp[0] * LOG2E; lb1 = lbp[SS] * LOG2E; }

    for (int kb = 0; kb < NBLK; ++kb) {
        asm volatile("bar.sync 0;" ::: "memory");   // block entry: ring/dfar visible
        const bool rescB = (kb > 0) && ((kb & 3) == 0);
        float fcor = 1.0f;
        if (rescB) {
            // per-column ring max (thread (cq, j) covers 32 slots of column j)
            float mx = 0.f;
#pragma unroll 4
            for (int s = 0; s < 32; ++s)
                mx = fmaxf(mx, ring[(32 * cq + s) * SS + j]);
            pmax[cq * SS + j] = mx;
            asm volatile("bar.sync 0;" ::: "memory");
            if (tid < 128) {
                float mv = fmaxf(fmaxf(pmax[j], pmax[SS + j]),
                                 fmaxf(pmax[2 * SS + j], pmax[3 * SS + j]));
                float dlt = lg2f(mv);
                R += dlt;
                float f = ex2f(-dlt);
                rs[j] = f;
                fcor = f;      // deep sums were computed pre-rescale
            }
            asm volatile("bar.sync 0;" ::: "memory");
            {
                float f = rs[j];
#pragma unroll 4
                for (int s = 0; s < 32; ++s)
                    ring[(32 * cq + s) * SS + j] *= f;
            }
            asm volatile("bar.sync 0;" ::: "memory");
        }

        if (tid < 256) {
            const int buf = kb & 1;
#pragma unroll 2
            for (int tau = 0; tau < 8; ++tau) {
                const int t = 8 * kb + tau;

                // ---- X: transition matvec partial over i in [64*cq, 64*cq+64) ----
                {
                    const float4* p4 = (const float4*)psh;
                    ull s0 = 0ull, s1 = 0ull, s2 = 0ull, s3 = 0ull;
#pragma unroll
                    for (int kk = 0; kk < 16; kk += 2) {
                        float4 v0 = p4[16 * cq + kk];
                        float4 v1 = p4[16 * cq + kk + 1];
                        ffma2(s0, packf2(v0.x, v0.y), P[2 * kk]);
                        ffma2(s1, packf2(v0.z, v0.w), P[2 * kk + 1]);
                        ffma2(s2, packf2(v1.x, v1.y), P[2 * kk + 2]);
                        ffma2(s3, packf2(v1.z, v1.w), P[2 * kk + 3]);
                    }
                    float a, b, c, d, e, f, g, h;
                    unpackf2(s0, a, b); unpackf2(s1, c, d);
                    unpackf2(s2, e, f); unpackf2(s3, g, h);
                    tp[cq * SS + j] = ((a + b) + (c + d)) + ((e + f) + (g + h));
                }
                asm volatile("bar.sync 2, 256;" ::: "memory");

                // ---- Y: scalar recurrence (warps 0-3) ----
                if (tid < 128) {
                    float lb_new = lbp[(size_t)min(t + 2, TT - 1) * SS] * LOG2E;

                    float entry;
                    if (t == 0) entry = pi2j;
                    else entry = m2h + lg2f(tp[j] + tp[SS + j]);
                    float vnew = ex2f(entry - cum2 - R);
                    ring[(t & 127) * SS + j] = vnew;

                    // near dot: d = 1..16 from own column (same-thread writes)
                    float nd = vnew * eDn[0];
#pragma unroll
                    for (int d = 2; d <= 16; ++d)
                        nd = fmaf(ring[((t + 8192 + 1 - d) & 127) * SS + j],
                                  eDn[d - 1], nd);

                    // deep dot: precomputed during previous block
                    const float* dfb = dfar + (buf * 4) * 8 * SS + tau * SS + j;
                    float dp = (dfb[0] + dfb[8 * SS]) +
                               (dfb[16 * SS] + dfb[24 * SS]);
                    float dot = nd + dp * fcor;

                    cum2 += lb0;                     // cum[t+1] in log2
                    if ((t & 15) == 15) {
                        alpha = cum2 + R + lg2f(dot);
                        float wm = alpha;
#pragma unroll
                        for (int o = 16; o; o >>= 1)
                            wm = fmaxf(wm, __shfl_xor_sync(0xffffffffu, wm, o));
                        if ((tid & 31) == 0) wred[tid >> 5] = wm;
                        asm volatile("bar.sync 1, 128;" ::: "memory");
                        m2h = fmaxf(fmaxf(wred[0], wred[1]),
                                    fmaxf(wred[2], wred[3]));
                    }
                    psh[j] = dot * ex2f(cum2 + R - m2h);
                    lb0 = lb1; lb1 = lb_new;
                }
                asm volatile("bar.sync 2, 256;" ::: "memory");
            }
        } else {
            // ---- Conv: deep duration sums for block kb+1 (slots <= 8*kb - 1) ----
            const int t0 = 8 * (kb + 1);
            const int d0 = 17 + 28 * cb;
            const int u0 = t0 - d0 - 26;             // lowest time index needed
            ull acc[8] = {0ull,0ull,0ull,0ull,0ull,0ull,0ull,0ull};
#pragma unroll
            for (int m = 0; m < 35; ++m) {
                ull v = *(const ull*)&ring[((u0 + m + 8192) & 127) * SS + 2 * cp];
#pragma unroll
                for (int tau = 0; tau < 8; ++tau) {
                    int q = tau + 27 - m;            // coeff index (d = d0+q)
                    if (q >= 0 && q <= 27) ffma2(acc[tau], v, P[q]);
                }
            }
            const int obuf = (kb + 1) & 1;
#pragma unroll
            for (int tau = 0; tau < 8; ++tau)
                *(ull*)&dfar[(obuf * 4 + cb) * 8 * SS + tau * SS + 2 * cp] = acc[tau];
        }
    }

    // loglik[b] = ln2 * log2sumexp2_j alpha[T-1][j]
    asm volatile("bar.sync 0;" ::: "memory");
    if (tid < 128) {
        float wm = alpha;
#pragma unroll
        for (int o = 16; o; o >>= 1)
            wm = fmaxf(wm, __shfl_xor_sync(0xffffffffu, wm, o));
        if ((tid & 31) == 0) wred[tid >> 5] = wm;
        asm volatile("bar.sync 1, 128;" ::: "memory");
        float m2f = fmaxf(fmaxf(wred[0], wred[1]), fmaxf(wred[2], wred[3]));
        float pe = ex2f(alpha - m2f);
#pragma unroll
        for (int o = 16; o; o >>= 1)
            pe += __shfl_xor_sync(0xffffffffu, pe, o);
        if ((tid & 31) == 0) wred[4 + (tid >> 5)] = pe;
        asm volatile("bar.sync 1, 128;" ::: "memory");
        if (tid == 0) {
            float ssum = (wred[4] + wred[5]) + (wred[6] + wred[7]);
            out[blockIdx.x] = (m2f + lg2f(ssum)) * LN2F;
        }
    }
}

extern "C" void kernel_launch(void* const* d_in, const int* in_sizes, int n_in,
                              void* d_out, int out_size) {
    const float* logB = (const float*)d_in[0];  // (B, T, S)
    const float* pi   = (const float*)d_in[1];  // (S,)
    const float* A    = (const float*)d_in[2];  // (S, S)
    const float* D    = (const float*)d_in[3];  // (S, DMAX)

    hsmm_precompute<<<128, 128>>>(A, D, pi);

    cudaFuncSetAttribute(hsmm_kernel,
                         cudaFuncAttributeMaxDynamicSharedMemorySize, SMEM_BYTES);
    hsmm_kernel<<<BB, 512, SMEM_BYTES>>>(logB, (float*)d_out);
}

// round 6
// speedup vs baseline: 3.6627x; 1.1474x over previous
#include <cuda_runtime.h>

#define SS   128
#define TT   2048
#define BB   64
#define NBLK 256              // TT / 8
#define LOG2E 1.4426950408889634f
#define LN2F  0.6931471805599453f

typedef unsigned long long ull;

// Static parameter transforms (shared across batches).
__device__ float g_expA[SS * SS];  // e^{A[i][j]}, [i][j]
__device__ float g_expD[SS * SS];  // e^{D[j][d-1]}, [d-1][j] (transposed)
__device__ float g_vpi[SS];        // e^{pi_j}  (exp-domain initial entry)

__device__ __forceinline__ float ex2f(float x) {
    float y; asm("ex2.approx.ftz.f32 %0, %1;" : "=f"(y) : "f"(x)); return y;
}
__device__ __forceinline__ float lg2f(float x) {
    float y; asm("lg2.approx.ftz.f32 %0, %1;" : "=f"(y) : "f"(x)); return y;
}
__device__ __forceinline__ ull packf2(float lo, float hi) {
    ull u; asm("mov.b64 %0, {%1, %2};" : "=l"(u) : "f"(lo), "f"(hi)); return u;
}
__device__ __forceinline__ void unpackf2(ull u, float& lo, float& hi) {
    asm("mov.b64 {%0, %1}, %2;" : "=f"(lo), "=f"(hi) : "l"(u));
}
__device__ __forceinline__ void ffma2(ull& d, ull a, ull b) {
    asm("fma.rn.f32x2 %0, %1, %2, %0;" : "+l"(d) : "l"(a), "l"(b));
}

__global__ void hsmm_precompute(const float* __restrict__ A,
                                const float* __restrict__ D,
                                const float* __restrict__ pi) {
    int r = blockIdx.x;   // 0..127
    int j = threadIdx.x;  // 0..127
    g_expA[r * SS + j] = expf(A[r * SS + j]);
    g_expD[r * SS + j] = expf(D[j * SS + r]);   // transpose; row r = duration r+1
    if (r == 0) g_vpi[j] = expf(pi[j]);
}

// Smem layout (floats):
#define OFF_RING 0        // ring[128][128]          16384
#define OFF_PSH  16384    // psh[128]
#define OFF_TP   16512    // tp[128]
#define OFF_DF   16640    // dfar[2][4][8][128]       8192
#define OFF_PM   24832    // pmax[4][128]              512
#define OFF_RS   25344    // rs[128]
#define OFF_WR   25472    // wred[8]
#define OFF_EDS  25480    // eDs[16][128]             2048
#define SMEM_FLOATS 27528
#define SMEM_BYTES  (SMEM_FLOATS * 4)

__global__ __launch_bounds__(512, 1)
void hsmm_kernel(const float* __restrict__ logB, float* __restrict__ out) {
    extern __shared__ float sm[];
    float* ring = sm + OFF_RING;
    float* psh  = sm + OFF_PSH;
    float* tp   = sm + OFF_TP;
    float* dfar = sm + OFF_DF;
    float* pmax = sm + OFF_PM;
    float* rs   = sm + OFF_RS;
    float* wred = sm + OFF_WR;
    float* eDs  = sm + OFF_EDS;

    const int tid  = threadIdx.x;
    const int j    = tid & 127;
    const int lane = tid & 31;
    const int wrp  = tid >> 5;

    // Unified register bank P[32]:
    //  tid <128 (Y):       eA pairs, states [0,64)
    //  tid 128-255 (help): eA pairs, states [64,128)
    //  tid >=256 (conv):   eD pairs for its 28-duration band (P[0..27])
    ull P[32];
    int cp = 0, cb = 0;
    if (tid < 256) {
        const int i0 = (tid < 128) ? 0 : 64;
#pragma unroll
        for (int k = 0; k < 32; ++k)
            P[k] = packf2(g_expA[(i0 + 2 * k) * SS + j],
                          g_expA[(i0 + 2 * k + 1) * SS + j]);
    } else {
        int g = tid - 256; cp = g & 63; cb = g >> 6;
        int d0 = 17 + 28 * cb;
#pragma unroll
        for (int q = 0; q < 28; ++q)
            P[q] = *(const ull*)&g_expD[(d0 + q - 1) * SS + 2 * cp];
    }

    // Zero ring (0 == exp-domain -inf; masks d > t+1), dfar; init psh, eDs.
    for (int k = tid; k < 16384; k += 512) ring[k] = 0.0f;
    for (int k = tid; k < 8192;  k += 512) dfar[k] = 0.0f;
    for (int k = tid; k < 2048;  k += 512) eDs[k]  = g_expD[k];
    if (tid < 128) psh[tid] = 0.0f;

    const float* lbp = logB + (size_t)blockIdx.x * TT * SS + j;

    // ---- Y per-state state (linear-domain scale tracking) ----
    float vh[15];
#pragma unroll
    for (int k = 0; k < 15; ++k) vh[k] = 0.0f;
    float w = 1.0f, rw = 1.0f;
    float frw_f = 1.0f, fw_f = 1.0f, fw_pend = 1.0f;
    float Cacc = 0.0f;
    float lb0 = 0.0f, lb1 = 0.0f, vpi = 0.0f, p_last = 0.0f;
    if (tid < 128) {
        lb0 = lbp[0];
        lb1 = lbp[SS];
        rw  = ex2f(lb0 * LOG2E);        // rw_0 = 2^{lb_0}
        vpi = g_vpi[j];
    }

    for (int kb = 0; kb < NBLK; ++kb) {
        asm volatile("bar.sync 0;" ::: "memory");   // block entry
        float fcor = 1.0f;
        const bool resc = (kb > 0) && ((kb & 3) == 0);
        if (resc) {
            const int cq = tid >> 7;
            float mxr = 0.0f;
#pragma unroll 4
            for (int s = 0; s < 32; ++s)
                mxr = fmaxf(mxr, ring[(32 * cq + s) * SS + j]);
            pmax[cq * SS + j] = mxr;
            asm volatile("bar.sync 0;" ::: "memory");
            if (tid < 128) {
                float mv = fmaxf(fmaxf(pmax[j], pmax[SS + j]),
                                 fmaxf(pmax[2 * SS + j], pmax[3 * SS + j]));
                int e = 0;
                if (mv > 0.0f) e = (__float_as_int(mv) >> 23) - 127;
                float rsv  = __int_as_float((127 - e) << 23);   // 2^{-e} exact
                float rsiv = __int_as_float((127 + e) << 23);   // 2^{+e} exact
                rs[j] = rsv;
                w  *= rsv;
                rw *= rsiv;
#pragma unroll
                for (int k = 0; k < 15; ++k) vh[k] *= rsv;
                fcor = rsv;            // deep sums were computed pre-rescale
            }
            asm volatile("bar.sync 0;" ::: "memory");
            {
                float f = rs[j];
#pragma unroll 4
                for (int s = 0; s < 32; ++s)
                    ring[(32 * cq + s) * SS + j] *= f;
            }
            asm volatile("bar.sync 0;" ::: "memory");
        }

        if (tid < 256) {
            // Y: preload this block's deep sums (computed last block by conv)
            float deepR[8];
            if (tid < 128) {
                const int buf = kb & 1;
#pragma unroll
                for (int tau = 0; tau < 8; ++tau) {
                    const float* dfb = dfar + ((buf * 4) * 8 + tau) * SS + j;
                    deepR[tau] = ((dfb[0] + dfb[8 * SS]) +
                                  (dfb[16 * SS] + dfb[24 * SS])) * fcor;
                }
            }
#pragma unroll
            for (int tau = 0; tau < 8; ++tau) {
                const int t = 8 * kb + tau;

                // ---- X: matvec partial over own 64-state band ----
                float tsum;
                {
                    const float4* p4 = (const float4*)psh;
                    const int base = (tid < 128) ? 0 : 16;
                    ull s0 = 0ull, s1 = 0ull, s2 = 0ull, s3 = 0ull;
#pragma unroll
                    for (int kk = 0; kk < 16; kk += 2) {
                        float4 v0 = p4[base + kk];
                        float4 v1 = p4[base + kk + 1];
                        ffma2(s0, packf2(v0.x, v0.y), P[2 * kk]);
                        ffma2(s1, packf2(v0.z, v0.w), P[2 * kk + 1]);
                        ffma2(s2, packf2(v1.x, v1.y), P[2 * kk + 2]);
                        ffma2(s3, packf2(v1.z, v1.w), P[2 * kk + 3]);
                    }
                    float a, b, c, d, e, f, g, h;
                    unpackf2(s0, a, b); unpackf2(s1, c, d);
                    unpackf2(s2, e, f); unpackf2(s3, g, h);
                    tsum = ((a + b) + (c + d)) + ((e + f) + (g + h));
                }
                if (tid >= 128) tp[j] = tsum;
                asm volatile("bar.sync 2, 256;" ::: "memory");   // bar A

                // ---- Y: MUFU-free serial recurrence ----
                if (tid < 128) {
                    // off-chain: input prefetch + scale-factor ex2's
                    float lbn = lbp[(size_t)min(t + 2, TT - 1) * SS];
                    float e2v = ex2f(lb1 * LOG2E);     // 2^{lb_{t+1}} for rw
                    float ebv = ex2f(-lb0 * LOG2E);    // 2^{-lb_t}   for w

                    // chain
                    float ts = tsum + tp[j];
                    float v  = (t == 0) ? vpi : ts * w;
                    ring[(t & 127) * SS + j] = v;

                    float n0 = v     * eDs[j];
                    float n1 = vh[0] * eDs[SS + j];
                    float n2 = vh[1] * eDs[2 * SS + j];
                    float n3 = vh[2] * eDs[3 * SS + j];
#pragma unroll
                    for (int d2 = 4; d2 < 16; d2 += 4) {
                        n0 = fmaf(vh[d2 - 1], eDs[(d2    ) * SS + j], n0);
                        n1 = fmaf(vh[d2    ], eDs[(d2 + 1) * SS + j], n1);
                        n2 = fmaf(vh[d2 + 1], eDs[(d2 + 2) * SS + j], n2);
                        n3 = fmaf(vh[d2 + 2], eDs[(d2 + 3) * SS + j], n3);
                    }
                    float dot = ((n0 + n1) + (n2 + n3)) + deepR[tau];
                    float p = dot * rw;
                    psh[j] = p;
                    p_last = p;

                    // history shift (register renaming under full unroll)
#pragma unroll
                    for (int k = 14; k > 0; --k) vh[k] = vh[k - 1];
                    vh[0] = v;

                    // psh renorm every 16 steps (exact power-of-2 factors)
                    if (tau == 7 && (kb & 1) == 1 && kb != NBLK - 1) {
                        unsigned um = __reduce_max_sync(0xffffffffu,
                                                        __float_as_uint(p));
                        if (lane == 0) wred[wrp] = __uint_as_float(um);
                        asm volatile("bar.sync 1, 128;" ::: "memory");
                        float mx = fmaxf(fmaxf(wred[0], wred[1]),
                                         fmaxf(wred[2], wred[3]));
                        int de = (__float_as_int(mx) >> 23) - 127;
                        Cacc += (float)de;
                        frw_f   = __int_as_float((127 - de) << 23);  // 2^{-de}
                        fw_pend = __int_as_float((127 + de) << 23);  // 2^{+de}
                    }

                    // end-of-step scale updates (off the next step's chain)
                    rw = rw * e2v * frw_f;  frw_f = 1.0f;
                    w  = w  * ebv * fw_f;   fw_f = fw_pend; fw_pend = 1.0f;
                    lb0 = lb1; lb1 = lbn;
                }
                asm volatile("bar.sync 2, 256;" ::: "memory");   // bar B
            }
        } else {
            // ---- Conv: deep duration sums (d=17..128) for block kb+1 ----
            const int t0 = 8 * (kb + 1);
            const int d0 = 17 + 28 * cb;
            const int u0 = t0 - d0 - 26;
            ull acc[8] = {0ull,0ull,0ull,0ull,0ull,0ull,0ull,0ull};
#pragma unroll
            for (int m = 0; m < 35; ++m) {
                ull v = *(const ull*)&ring[((u0 + m + 8192) & 127) * SS + 2 * cp];
#pragma unroll
                for (int tau = 0; tau < 8; ++tau) {
                    int q = tau + 27 - m;
                    if (q >= 0 && q <= 27) ffma2(acc[tau], v, P[q]);
                }
            }
            const int obuf = (kb + 1) & 1;
#pragma unroll
            for (int tau = 0; tau < 8; ++tau)
                *(ull*)&dfar[((obuf * 4 + cb) * 8 + tau) * SS + 2 * cp] = acc[tau];
        }
    }

    // loglik[b] = ln2 * (Cacc + lg2(sum_j psh_j))
    asm volatile("bar.sync 0;" ::: "memory");
    if (tid < 128) {
        float s = p_last;
#pragma unroll
        for (int o = 16; o; o >>= 1)
            s += __shfl_xor_sync(0xffffffffu, s, o);
        if (lane == 0) wred[wrp] = s;
        asm volatile("bar.sync 1, 128;" ::: "memory");
        if (tid == 0) {
            float tot = (wred[0] + wred[1]) + (wred[2] + wred[3]);
            out[blockIdx.x] = (Cacc + lg2f(tot)) * LN2F;
        }
    }
}

extern "C" void kernel_launch(void* const* d_in, const int* in_sizes, int n_in,
                              void* d_out, int out_size) {
    const float* logB = (const float*)d_in[0];  // (B, T, S)
    const float* pi   = (const float*)d_in[1];  // (S,)
    const float* A    = (const float*)d_in[2];  // (S, S)
    const float* D    = (const float*)d_in[3];  // (S, DMAX)

    hsmm_precompute<<<128, 128>>>(A, D, pi);

    cudaFuncSetAttribute(hsmm_kernel,
                         cudaFuncAttributeMaxDynamicSharedMemorySize, SMEM_BYTES);
    hsmm_kernel<<<BB, 512, SMEM_BYTES>>>(logB, (float*)d_out);
}